// round 1
// baseline (speedup 1.0000x reference)
#include <cuda_runtime.h>
#include <cstdint>

#define SEQ 4096
#define FEAT 4096
#define DENSE 4096
#define EMB 50
#define G3 150          // 3*EMB
#define GS 160          // padded gi1 row stride

// ---------------- scratch (device globals; no allocation allowed) ----------------
__device__ float d_G[SEQ * GS];     // gi1 for every step (includes g_dense + b_ih1)
__device__ float d_gden[GS];        // dense contribution + b_ih1
__device__ float d_H2[SEQ * EMB];   // h2 per step

// ---------------- kernel 1: g_dense = W_ih1[:, :4096] @ dense + b_ih1 ----------------
__global__ void gdense_kernel(const float* __restrict__ dense,
                              const float* __restrict__ W_ih1,
                              const float* __restrict__ b_ih1) {
    __shared__ float red[256];
    int j = blockIdx.x;           // 0..149
    int tid = threadIdx.x;
    float s = 0.f;
    const float* wrow = W_ih1 + (size_t)j * (DENSE + FEAT);
    for (int k = tid; k < DENSE; k += 256) s += dense[k] * wrow[k];
    red[tid] = s;
    __syncthreads();
    for (int off = 128; off > 0; off >>= 1) {
        if (tid < off) red[tid] += red[tid + off];
        __syncthreads();
    }
    if (tid == 0) d_gden[j] = red[0] + b_ih1[j];
}

// ---------------- kernel 2: d_G[t][j] = gden[j] + onehot[t-1] . W_ih1[j, 4096:] ----------------
// BM=32 t-rows per block, all 150 cols, BK=32. 160 threads, 8x4 register tile.
__global__ void __launch_bounds__(160) gemm_fb_kernel(const float* __restrict__ onehot,
                                                      const float* __restrict__ W_ih1) {
    __shared__ float As[32 * 36];    // [kk][r], stride 36
    __shared__ float Bs[32 * 164];   // [kk][j], stride 164
    int t0 = blockIdx.x * 32;
    int tid = threadIdx.x;
    int rg = tid / 40;       // 0..3  -> rows rg*8 .. rg*8+7
    int jg = tid % 40;       // 0..39 -> cols jg*4 .. jg*4+3

    float acc[8][4];
#pragma unroll
    for (int r = 0; r < 8; r++)
#pragma unroll
        for (int c = 0; c < 4; c++) acc[r][c] = 0.f;

    for (int k0 = 0; k0 < FEAT; k0 += 32) {
        // load A tile: fb rows (fb[t] = onehot[t-1], fb[0]=0)
        for (int idx = tid; idx < 32 * 32; idx += 160) {
            int r = idx >> 5, kk = idx & 31;
            int t = t0 + r;
            As[kk * 36 + r] = (t >= 1) ? onehot[(size_t)(t - 1) * FEAT + k0 + kk] : 0.f;
        }
        // load B tile: W_ih1[j, 4096 + k0 + kk]
        for (int idx = tid; idx < G3 * 32; idx += 160) {
            int j = idx >> 5, kk = idx & 31;
            Bs[kk * 164 + j] = W_ih1[(size_t)j * (DENSE + FEAT) + DENSE + k0 + kk];
        }
        __syncthreads();
#pragma unroll
        for (int kk = 0; kk < 32; kk++) {
            float4 a0 = *(const float4*)&As[kk * 36 + rg * 8];
            float4 a1 = *(const float4*)&As[kk * 36 + rg * 8 + 4];
            float4 b  = *(const float4*)&Bs[kk * 164 + jg * 4];
            float av[8] = {a0.x, a0.y, a0.z, a0.w, a1.x, a1.y, a1.z, a1.w};
            float bv[4] = {b.x, b.y, b.z, b.w};
#pragma unroll
            for (int r = 0; r < 8; r++)
#pragma unroll
                for (int c = 0; c < 4; c++) acc[r][c] += av[r] * bv[c];
        }
        __syncthreads();
    }
#pragma unroll
    for (int r = 0; r < 8; r++) {
        int t = t0 + rg * 8 + r;
#pragma unroll
        for (int c = 0; c < 4; c++) {
            int j = jg * 4 + c;
            if (j < G3) d_G[t * GS + j] = acc[r][c] + d_gden[j];
        }
    }
}

// ---------------- kernel 3: the sequential GRU scan (1 block, 512 threads) ----------------
__device__ __forceinline__ float sigm(float x) {
    return __fdividef(1.f, 1.f + __expf(-x));
}
__device__ __forceinline__ float tanh_fast(float x) {
    return 2.f * __fdividef(1.f, 1.f + __expf(-2.f * x)) - 1.f;
}

__global__ void __launch_bounds__(512, 1) scan_kernel(const float* __restrict__ W_hh1,
                                                      const float* __restrict__ b_hh1,
                                                      const float* __restrict__ W_ih2,
                                                      const float* __restrict__ b_ih2,
                                                      const float* __restrict__ W_hh2,
                                                      const float* __restrict__ b_hh2) {
    __shared__ __align__(16) float h1s[64];
    __shared__ __align__(16) float h2s[64];
    __shared__ __align__(16) float gh1[G3 + 2];
    __shared__ __align__(16) float gh2[G3 + 2];
    __shared__ __align__(16) float gi2[G3 + 2];
    __shared__ __align__(16) float gi1buf[2][GS];

    int tid = threadIdx.x;

    // role assignment: 0-149 -> gh1 (W_hh1), 160-309 -> gi2 (W_ih2), 320-469 -> gh2 (W_hh2)
    const float* wsrc = nullptr;
    float bias = 0.f;
    if (tid < G3)                      { wsrc = W_hh1 + tid * EMB;        bias = b_hh1[tid]; }
    else if (tid >= 160 && tid < 310)  { wsrc = W_ih2 + (tid - 160) * EMB; bias = b_ih2[tid - 160]; }
    else if (tid >= 320 && tid < 470)  { wsrc = W_hh2 + (tid - 320) * EMB; bias = b_hh2[tid - 320]; }

    float w[EMB];
    if (wsrc) {
#pragma unroll
        for (int k = 0; k < EMB; k++) w[k] = wsrc[k];
    }

    if (tid < 64) { h1s[tid] = 0.f; h2s[tid] = 0.f; }
    // prefetch gi1 row 0
    if (tid >= 470 && tid < 502) {
        for (int i = tid - 470; i < G3; i += 32) gi1buf[0][i] = d_G[i];
    }
    __syncthreads();

    for (int t = 0; t < SEQ; t++) {
        const float* gi1 = gi1buf[t & 1];

        // ---- stage A: gh1 = W_hh1 . h1 ; gh2 = W_hh2 . h2 ; prefetch next gi1 row
        if (tid < G3) {
            float a = bias;
#pragma unroll
            for (int k = 0; k < EMB; k++) a += w[k] * h1s[k];
            gh1[tid] = a;
        } else if (tid >= 320 && tid < 470) {
            float a = bias;
#pragma unroll
            for (int k = 0; k < EMB; k++) a += w[k] * h2s[k];
            gh2[tid - 320] = a;
        } else if (tid >= 470 && tid < 502) {
            if (t + 1 < SEQ) {
                const float* src = d_G + (t + 1) * GS;
                float* dst = gi1buf[(t + 1) & 1];
                for (int i = tid - 470; i < G3; i += 32) dst[i] = src[i];
            }
        }
        __syncthreads();

        // ---- stage B: h1 update
        if (tid < EMB) {
            float r = sigm(gi1[tid] + gh1[tid]);
            float z = sigm(gi1[EMB + tid] + gh1[EMB + tid]);
            float n = tanh_fast(gi1[2 * EMB + tid] + r * gh1[2 * EMB + tid]);
            h1s[tid] = (1.f - z) * n + z * h1s[tid];
        }
        __syncthreads();

        // ---- stage C: gi2 = W_ih2 . h1_new
        if (tid >= 160 && tid < 310) {
            float a = bias;
#pragma unroll
            for (int k = 0; k < EMB; k++) a += w[k] * h1s[k];
            gi2[tid - 160] = a;
        }
        __syncthreads();

        // ---- stage D: h2 update + store
        if (tid < EMB) {
            float r = sigm(gi2[tid] + gh2[tid]);
            float z = sigm(gi2[EMB + tid] + gh2[EMB + tid]);
            float n = tanh_fast(gi2[2 * EMB + tid] + r * gh2[2 * EMB + tid]);
            float h2 = (1.f - z) * n + z * h2s[tid];
            h2s[tid] = h2;
            d_H2[t * EMB + tid] = h2;
        }
        __syncthreads();
    }
}

// ---------------- kernel 4: out[t][f] = b2[f] + H2[t] . W2[f] ----------------
__global__ void __launch_bounds__(256) out_gemm_kernel(const float* __restrict__ W2,
                                                       const float* __restrict__ b2,
                                                       float* __restrict__ out) {
    __shared__ __align__(16) float Hs[EMB * 68];  // [k][t] stride 68
    __shared__ __align__(16) float Ws[EMB * 68];  // [k][f] stride 68
    int t0 = blockIdx.y * 64;
    int f0 = blockIdx.x * 64;
    int tid = threadIdx.x;

    for (int idx = tid; idx < 64 * EMB; idx += 256) {
        int tt = idx / EMB, k = idx % EMB;
        Hs[k * 68 + tt] = d_H2[(t0 + tt) * EMB + k];
    }
    for (int idx = tid; idx < 64 * EMB; idx += 256) {
        int ff = idx / EMB, k = idx % EMB;
        Ws[k * 68 + ff] = W2[(size_t)(f0 + ff) * EMB + k];
    }
    __syncthreads();

    int tg = tid / 16;   // row group: 4 rows
    int fg = tid % 16;   // col group: 4 cols
    float acc[4][4];
#pragma unroll
    for (int i = 0; i < 4; i++)
#pragma unroll
        for (int jx = 0; jx < 4; jx++) acc[i][jx] = 0.f;

#pragma unroll
    for (int k = 0; k < EMB; k++) {
        float4 h = *(const float4*)&Hs[k * 68 + tg * 4];
        float4 wv = *(const float4*)&Ws[k * 68 + fg * 4];
        float hv[4] = {h.x, h.y, h.z, h.w};
        float wf[4] = {wv.x, wv.y, wv.z, wv.w};
#pragma unroll
        for (int i = 0; i < 4; i++)
#pragma unroll
            for (int jx = 0; jx < 4; jx++) acc[i][jx] += hv[i] * wf[jx];
    }

    float4 bb = *(const float4*)&b2[f0 + fg * 4];
#pragma unroll
    for (int i = 0; i < 4; i++) {
        float4 v;
        v.x = acc[i][0] + bb.x;
        v.y = acc[i][1] + bb.y;
        v.z = acc[i][2] + bb.z;
        v.w = acc[i][3] + bb.w;
        *(float4*)&out[(size_t)(t0 + tg * 4 + i) * FEAT + f0 + fg * 4] = v;
    }
}

// ---------------- launch ----------------
extern "C" void kernel_launch(void* const* d_in, const int* in_sizes, int n_in,
                              void* d_out, int out_size) {
    // Locate inputs by element-count fingerprint (robust to scalar entries).
    const float *dense = nullptr, *onehot = nullptr, *W_ih1 = nullptr, *W_hh1 = nullptr,
                *b_ih1 = nullptr, *b_hh1 = nullptr, *W_ih2 = nullptr, *W_hh2 = nullptr,
                *b_ih2 = nullptr, *b_hh2 = nullptr, *W2 = nullptr, *b2 = nullptr;
    int c4096 = 0, c7500 = 0, c150 = 0, cbig = 0;
    for (int i = 0; i < n_in; i++) {
        int s = in_sizes[i];
        const float* p = (const float*)d_in[i];
        if (s == 4096) {                 // input_dense, b1(dead), b2 in order
            if (c4096 == 0) dense = p;
            else if (c4096 == 2) b2 = p;
            c4096++;
        } else if (s == 16777216) {      // input_onehot, W1(dead) in order
            if (cbig == 0) onehot = p;
            cbig++;
        } else if (s == 1228800) {
            W_ih1 = p;
        } else if (s == 7500) {          // W_hh1, W_ih2, W_hh2 in order
            if (c7500 == 0) W_hh1 = p;
            else if (c7500 == 1) W_ih2 = p;
            else W_hh2 = p;
            c7500++;
        } else if (s == 150) {           // b_ih1, b_hh1, b_ih2, b_hh2 in order
            if (c150 == 0) b_ih1 = p;
            else if (c150 == 1) b_hh1 = p;
            else if (c150 == 2) b_ih2 = p;
            else b_hh2 = p;
            c150++;
        } else if (s == 204800) {
            W2 = p;
        }
    }

    float* out = (float*)d_out;

    gdense_kernel<<<G3, 256>>>(dense, W_ih1, b_ih1);
    gemm_fb_kernel<<<SEQ / 32, 160>>>(onehot, W_ih1);
    scan_kernel<<<1, 512>>>(W_hh1, b_hh1, W_ih2, b_ih2, W_hh2, b_hh2);
    out_gemm_kernel<<<dim3(FEAT / 64, SEQ / 64), 256>>>(W2, b2, out);
}

// round 3
// speedup vs baseline: 1.7869x; 1.7869x over previous
#include <cuda_runtime.h>
#include <cstdint>

#define SEQ 4096
#define FEAT 4096
#define DENSE 4096
#define EMB 50
#define G3 150          // 3*EMB
#define GS 160          // padded gi1 row stride

// ---------------- scratch (device globals; no allocation allowed) ----------------
__device__ float d_G[SEQ * GS];     // gi1 for every step (includes g_dense + b_ih1)
__device__ float d_gden[GS];        // dense contribution + b_ih1
__device__ float d_H2[SEQ * EMB];   // h2 per step

// ---------------- kernel 1: g_dense = W_ih1[:, :4096] @ dense + b_ih1 ----------------
__global__ void gdense_kernel(const float* __restrict__ dense,
                              const float* __restrict__ W_ih1,
                              const float* __restrict__ b_ih1) {
    __shared__ float red[256];
    int j = blockIdx.x;           // 0..149
    int tid = threadIdx.x;
    float s = 0.f;
    const float* wrow = W_ih1 + (size_t)j * (DENSE + FEAT);
    for (int k = tid; k < DENSE; k += 256) s += dense[k] * wrow[k];
    red[tid] = s;
    __syncthreads();
    for (int off = 128; off > 0; off >>= 1) {
        if (tid < off) red[tid] += red[tid + off];
        __syncthreads();
    }
    if (tid == 0) d_gden[j] = red[0] + b_ih1[j];
}

// ---------------- kernel 2: d_G[t][j] = gden[j] + onehot[t-1] . W_ih1[j, 4096:] ----------------
__global__ void __launch_bounds__(160) gemm_fb_kernel(const float* __restrict__ onehot,
                                                      const float* __restrict__ W_ih1) {
    __shared__ float As[32 * 36];    // [kk][r], stride 36
    __shared__ float Bs[32 * 164];   // [kk][j], stride 164
    int t0 = blockIdx.x * 32;
    int tid = threadIdx.x;
    int rg = tid / 40;       // 0..3  -> rows rg*8 .. rg*8+7
    int jg = tid % 40;       // 0..39 -> cols jg*4 .. jg*4+3

    float acc[8][4];
#pragma unroll
    for (int r = 0; r < 8; r++)
#pragma unroll
        for (int c = 0; c < 4; c++) acc[r][c] = 0.f;

    for (int k0 = 0; k0 < FEAT; k0 += 32) {
        for (int idx = tid; idx < 32 * 32; idx += 160) {
            int r = idx >> 5, kk = idx & 31;
            int t = t0 + r;
            As[kk * 36 + r] = (t >= 1) ? onehot[(size_t)(t - 1) * FEAT + k0 + kk] : 0.f;
        }
        for (int idx = tid; idx < G3 * 32; idx += 160) {
            int j = idx >> 5, kk = idx & 31;
            Bs[kk * 164 + j] = W_ih1[(size_t)j * (DENSE + FEAT) + DENSE + k0 + kk];
        }
        __syncthreads();
#pragma unroll
        for (int kk = 0; kk < 32; kk++) {
            float4 a0 = *(const float4*)&As[kk * 36 + rg * 8];
            float4 a1 = *(const float4*)&As[kk * 36 + rg * 8 + 4];
            float4 b  = *(const float4*)&Bs[kk * 164 + jg * 4];
            float av[8] = {a0.x, a0.y, a0.z, a0.w, a1.x, a1.y, a1.z, a1.w};
            float bv[4] = {b.x, b.y, b.z, b.w};
#pragma unroll
            for (int r = 0; r < 8; r++)
#pragma unroll
                for (int c = 0; c < 4; c++) acc[r][c] += av[r] * bv[c];
        }
        __syncthreads();
    }
#pragma unroll
    for (int r = 0; r < 8; r++) {
        int t = t0 + rg * 8 + r;
#pragma unroll
        for (int c = 0; c < 4; c++) {
            int j = jg * 4 + c;
            if (j < G3) d_G[t * GS + j] = acc[r][c] + d_gden[j];
        }
    }
}

// ---------------- kernel 3: the sequential GRU scan (1 block, 512 threads) ----------------
__device__ __forceinline__ float sigm(float x) {
    return __fdividef(1.f, 1.f + __expf(-x));
}
__device__ __forceinline__ float tanh_fast(float x) {
    return 2.f * __fdividef(1.f, 1.f + __expf(-2.f * x)) - 1.f;
}

__device__ __forceinline__ unsigned long long fma2(unsigned long long a,
                                                   unsigned long long b,
                                                   unsigned long long c) {
    unsigned long long d;
    asm("fma.rn.f32x2 %0, %1, %2, %3;" : "=l"(d) : "l"(a), "l"(b), "l"(c));
    return d;
}
__device__ __forceinline__ unsigned long long packf2(float lo, float hi) {
    unsigned long long r;
    asm("mov.b64 %0, {%1, %2};" : "=l"(r) : "r"(__float_as_uint(lo)), "r"(__float_as_uint(hi)));
    return r;
}
__device__ __forceinline__ float lo32(unsigned long long v) {
    return __uint_as_float((unsigned)(v & 0xffffffffull));
}
__device__ __forceinline__ float hi32(unsigned long long v) {
    return __uint_as_float((unsigned)(v >> 32));
}

// 50-dim dot: h padded to 52 floats (16B aligned), wp = 26 packed pairs (last zero)
__device__ __forceinline__ float dot50(const unsigned long long* __restrict__ wp,
                                       const float* __restrict__ h) {
    unsigned long long acc0 = 0ull, acc1 = 0ull;
    const ulonglong2* hp = (const ulonglong2*)h;
#pragma unroll
    for (int q = 0; q < 13; q++) {
        ulonglong2 hq = hp[q];
        acc0 = fma2(wp[2 * q], hq.x, acc0);
        acc1 = fma2(wp[2 * q + 1], hq.y, acc1);
    }
    return lo32(acc0) + hi32(acc0) + lo32(acc1) + hi32(acc1);
}

__global__ void __launch_bounds__(512, 1) scan_kernel(const float* __restrict__ W_hh1,
                                                      const float* __restrict__ b_hh1,
                                                      const float* __restrict__ W_ih2,
                                                      const float* __restrict__ b_ih2,
                                                      const float* __restrict__ W_hh2,
                                                      const float* __restrict__ b_hh2) {
    __shared__ __align__(16) float h1buf[2][52];
    __shared__ __align__(16) float h2s[52];
    __shared__ __align__(16) float gh1[152];
    __shared__ __align__(16) float gh2[152];
    __shared__ __align__(16) float gi2buf[2][152];
    __shared__ __align__(16) float gi1buf[2][GS];

    int tid = threadIdx.x;

    // roles: A = warps 0-4 (tid<160): gh1 + act1
    //        B = warps 5-9 (160-319): gi2
    //        C = warps 10-14 (320-479): gh2 + act2 + store
    //        P = warp 15 (480-511): gi1 prefetch
    // barriers: bar1 = A (160); bar2 = A+B+P (352); bar3 = B+C (320); bar4 = C (160)
    const float* wsrc = nullptr;
    const float* bsrc = nullptr;
    int j = 0;
    if (tid < 160)       { if (tid < 150) { wsrc = W_hh1; bsrc = b_hh1; j = tid; } }
    else if (tid < 320)  { if (tid < 310) { wsrc = W_ih2; bsrc = b_ih2; j = tid - 160; } }
    else if (tid < 480)  { if (tid < 470) { wsrc = W_hh2; bsrc = b_hh2; j = tid - 320; } }

    unsigned long long wp[26];
    float bias = 0.f;
    if (wsrc) {
        const float* row = wsrc + j * EMB;
#pragma unroll
        for (int k = 0; k < 25; k++) wp[k] = packf2(row[2 * k], row[2 * k + 1]);
        wp[25] = 0ull;
        bias = bsrc[j];
    } else {
#pragma unroll
        for (int k = 0; k < 26; k++) wp[k] = 0ull;
    }

    if (tid < 52) { h1buf[0][tid] = 0.f; h1buf[1][tid] = 0.f; h2s[tid] = 0.f; }
    if (tid >= 480) {
        int l = tid - 480;
        const float4* src = (const float4*)d_G;
        float4* dst = (float4*)gi1buf[0];
        for (int i = l; i < 38; i += 32) dst[i] = src[i];
    }
    __syncthreads();

    for (int t = 0; t < SEQ; t++) {
        int b = t & 1;
        if (tid < 160) {
            if (tid < 150) gh1[tid] = dot50(wp, h1buf[b ^ 1]) + bias;
            asm volatile("bar.sync 1, 160;" ::: "memory");
            if (tid < EMB) {
                const float* gi1 = gi1buf[b];
                float r = sigm(gi1[tid] + gh1[tid]);
                float z = sigm(gi1[EMB + tid] + gh1[EMB + tid]);
                float n = tanh_fast(gi1[2 * EMB + tid] + r * gh1[2 * EMB + tid]);
                h1buf[b][tid] = (1.f - z) * n + z * h1buf[b ^ 1][tid];
            }
            asm volatile("bar.sync 2, 352;" ::: "memory");
        } else if (tid < 320) {
            asm volatile("bar.sync 2, 352;" ::: "memory");
            if (tid < 310) gi2buf[b][tid - 160] = dot50(wp, h1buf[b]) + bias;
            asm volatile("bar.sync 3, 320;" ::: "memory");
        } else if (tid < 480) {
            if (tid < 470) gh2[tid - 320] = dot50(wp, h2s) + bias;
            asm volatile("bar.sync 3, 320;" ::: "memory");
            if (tid < 320 + EMB) {
                int jj = tid - 320;
                const float* gi2 = gi2buf[b];
                float r = sigm(gi2[jj] + gh2[jj]);
                float z = sigm(gi2[EMB + jj] + gh2[EMB + jj]);
                float n = tanh_fast(gi2[2 * EMB + jj] + r * gh2[2 * EMB + jj]);
                float h2 = (1.f - z) * n + z * h2s[jj];
                h2s[jj] = h2;
                d_H2[t * EMB + jj] = h2;
            }
            asm volatile("bar.sync 4, 160;" ::: "memory");
        } else {
            if (t + 1 < SEQ) {
                int l = tid - 480;
                const float4* src = (const float4*)(d_G + (size_t)(t + 1) * GS);
                float4* dst = (float4*)gi1buf[b ^ 1];
                for (int i = l; i < 38; i += 32) dst[i] = src[i];
            }
            asm volatile("bar.sync 2, 352;" ::: "memory");
        }
    }
}

// ---------------- kernel 4: out[t][f] = b2[f] + H2[t] . W2[f] ----------------
__global__ void __launch_bounds__(256) out_gemm_kernel(const float* __restrict__ W2,
                                                       const float* __restrict__ b2,
                                                       float* __restrict__ out) {
    __shared__ __align__(16) float Hs[EMB * 68];  // [k][t] stride 68
    __shared__ __align__(16) float Ws[EMB * 68];  // [k][f] stride 68
    int t0 = blockIdx.y * 64;
    int f0 = blockIdx.x * 64;
    int tid = threadIdx.x;

    for (int idx = tid; idx < 64 * EMB; idx += 256) {
        int tt = idx / EMB, k = idx % EMB;
        Hs[k * 68 + tt] = d_H2[(t0 + tt) * EMB + k];
    }
    for (int idx = tid; idx < 64 * EMB; idx += 256) {
        int ff = idx / EMB, k = idx % EMB;
        Ws[k * 68 + ff] = W2[(size_t)(f0 + ff) * EMB + k];
    }
    __syncthreads();

    int tg = tid / 16;
    int fg = tid % 16;
    float acc[4][4];
#pragma unroll
    for (int i = 0; i < 4; i++)
#pragma unroll
        for (int jx = 0; jx < 4; jx++) acc[i][jx] = 0.f;

#pragma unroll
    for (int k = 0; k < EMB; k++) {
        float4 h = *(const float4*)&Hs[k * 68 + tg * 4];
        float4 wv = *(const float4*)&Ws[k * 68 + fg * 4];
        float hv[4] = {h.x, h.y, h.z, h.w};
        float wf[4] = {wv.x, wv.y, wv.z, wv.w};
#pragma unroll
        for (int i = 0; i < 4; i++)
#pragma unroll
            for (int jx = 0; jx < 4; jx++) acc[i][jx] += hv[i] * wf[jx];
    }

    float4 bb = *(const float4*)&b2[f0 + fg * 4];
#pragma unroll
    for (int i = 0; i < 4; i++) {
        float4 v;
        v.x = acc[i][0] + bb.x;
        v.y = acc[i][1] + bb.y;
        v.z = acc[i][2] + bb.z;
        v.w = acc[i][3] + bb.w;
        *(float4*)&out[(size_t)(t0 + tg * 4 + i) * FEAT + f0 + fg * 4] = v;
    }
}

// ---------------- launch ----------------
extern "C" void kernel_launch(void* const* d_in, const int* in_sizes, int n_in,
                              void* d_out, int out_size) {
    const float *dense = nullptr, *onehot = nullptr, *W_ih1 = nullptr, *W_hh1 = nullptr,
                *b_ih1 = nullptr, *b_hh1 = nullptr, *W_ih2 = nullptr, *W_hh2 = nullptr,
                *b_ih2 = nullptr, *b_hh2 = nullptr, *W2 = nullptr, *b2 = nullptr;
    int c4096 = 0, c7500 = 0, c150 = 0, cbig = 0;
    for (int i = 0; i < n_in; i++) {
        int s = in_sizes[i];
        const float* p = (const float*)d_in[i];
        if (s == 4096) {
            if (c4096 == 0) dense = p;
            else if (c4096 == 2) b2 = p;
            c4096++;
        } else if (s == 16777216) {
            if (cbig == 0) onehot = p;
            cbig++;
        } else if (s == 1228800) {
            W_ih1 = p;
        } else if (s == 7500) {
            if (c7500 == 0) W_hh1 = p;
            else if (c7500 == 1) W_ih2 = p;
            else W_hh2 = p;
            c7500++;
        } else if (s == 150) {
            if (c150 == 0) b_ih1 = p;
            else if (c150 == 1) b_hh1 = p;
            else if (c150 == 2) b_ih2 = p;
            else b_hh2 = p;
            c150++;
        } else if (s == 204800) {
            W2 = p;
        }
    }

    float* out = (float*)d_out;

    gdense_kernel<<<G3, 256>>>(dense, W_ih1, b_ih1);
    gemm_fb_kernel<<<SEQ / 32, 160>>>(onehot, W_ih1);
    scan_kernel<<<1, 512>>>(W_hh1, b_hh1, W_ih2, b_ih2, W_hh2, b_hh2);
    out_gemm_kernel<<<dim3(FEAT / 64, SEQ / 64), 256>>>(W2, b2, out);
}